// round 3
// baseline (speedup 1.0000x reference)
#include <cuda_runtime.h>

#define CDIV(a,b) (((a)+(b)-1)/(b))

#define NN 100000
#define NE 1600000

// ---------------- device scratch (static; no cudaMalloc) ----------------
__device__ int   g_deg[NN];
__device__ int   g_off[NN + 1];
__device__ int   g_cur[NN];
__device__ int   g_csr[NE];
__device__ float g_agg[(size_t)NN * 64];
__device__ float g_h0 [(size_t)NN * 64];
__device__ float g_h1 [(size_t)NN * 64];

// buffer selector (resolved in device code; never take symbol addresses on host)
__device__ __forceinline__ const float* sel_buf(int s, const float* ext) {
    return s == 0 ? ext : (s == 1 ? g_h0 : g_h1);
}

// ---------------- CSR construction ----------------
__global__ void k_zero_deg() {
    int i = blockIdx.x * blockDim.x + threadIdx.x;
    if (i < NN) g_deg[i] = 0;
}

__global__ void k_count(const int* __restrict__ ei) {
    int e = blockIdx.x * blockDim.x + threadIdx.x;
    if (e < NE) {
        int dst = ei[NE + e];   // edge_index row 1 = dst (int32!)
        atomicAdd(&g_deg[dst], 1);
    }
}

// single-block exclusive scan over 100k degrees (1024 threads x 98-elem chunks)
__global__ void k_scan() {
    __shared__ int sums[1024];
    const int CH = 98;  // 1024*98 = 100352 >= NN
    int t = threadIdx.x;
    int b = t * CH;
    int e = min(b + CH, NN);
    int s = 0;
    for (int i = b; i < e; i++) s += g_deg[i];
    sums[t] = s;
    __syncthreads();
    for (int o = 1; o < 1024; o <<= 1) {
        int v = (t >= o) ? sums[t - o] : 0;
        __syncthreads();
        sums[t] += v;
        __syncthreads();
    }
    int run = (t == 0) ? 0 : sums[t - 1];
    for (int i = b; i < e; i++) {
        g_off[i] = run;
        g_cur[i] = run;
        run += g_deg[i];
    }
    if (t == 1023) g_off[NN] = run;
}

__global__ void k_scatter(const int* __restrict__ ei) {
    int e = blockIdx.x * blockDim.x + threadIdx.x;
    if (e < NE) {
        int src = ei[e];
        int dst = ei[NE + e];
        int p = atomicAdd(&g_cur[dst], 1);
        g_csr[p] = src;
    }
}

// ---------------- mean aggregation: warp per destination node ----------------
// Each lane owns 2 channels (float2). Per edge the warp reads one contiguous
// 256B feature row (L2-resident), accumulates, then scales by 1/max(deg,1).
__global__ void k_agg(const float* __restrict__ xext, int xsel) {
    int gw   = (blockIdx.x * blockDim.x + threadIdx.x) >> 5;
    int lane = threadIdx.x & 31;
    if (gw >= NN) return;
    const float* __restrict__ x = sel_buf(xsel, xext);
    int beg = g_off[gw];
    int end = g_off[gw + 1];
    const float2* __restrict__ x2 = (const float2*)x;
    float sx = 0.f, sy = 0.f;
    int e = beg;
    #pragma unroll 1
    for (; e + 4 <= end; e += 4) {
        int s0 = g_csr[e + 0];
        int s1 = g_csr[e + 1];
        int s2 = g_csr[e + 2];
        int s3 = g_csr[e + 3];
        float2 v0 = x2[(size_t)s0 * 32 + lane];
        float2 v1 = x2[(size_t)s1 * 32 + lane];
        float2 v2 = x2[(size_t)s2 * 32 + lane];
        float2 v3 = x2[(size_t)s3 * 32 + lane];
        sx += v0.x + v1.x + v2.x + v3.x;
        sy += v0.y + v1.y + v2.y + v3.y;
    }
    for (; e < end; ++e) {
        int s = g_csr[e];
        float2 v = x2[(size_t)s * 32 + lane];
        sx += v.x;
        sy += v.y;
    }
    int d = end - beg;
    float inv = d > 0 ? 1.f / (float)d : 0.f;
    float2 o;
    o.x = sx * inv;
    o.y = sy * inv;
    ((float2*)g_agg)[(size_t)gw * 32 + lane] = o;
}

// ---------------- fused GEMM: out = [agg | A1] @ [B0;B1] + bias (, ReLU) ----------------
// M=100000, K = KTOT (128: 64 agg + 64 root; 64 for final), N = NOUT.
// Block tile 128xNOUT, 128 threads, 8xCN register tile. A staged transposed in
// smem (As[k][m], LDA=132 pad) so frag loads are float4.
template <int KTOT, int NOUT, bool RELU, bool SPLIT>
__global__ void __launch_bounds__(128)
k_gemm(const float* __restrict__ xext, int asel, int dsel,
       const float* __restrict__ B0, const float* __restrict__ B1,
       const float* __restrict__ bias, float* __restrict__ oext) {
    constexpr int BM  = 128;
    constexpr int LDA = 132;
    constexpr int CN  = NOUT / 8;
    __shared__ float As[32][LDA];
    __shared__ float Bs[32][NOUT];

    const float* __restrict__ A1 = sel_buf(asel, xext);
    const float* __restrict__ A0 = SPLIT ? (const float*)g_agg : A1;
    float* __restrict__ out = (dsel == 0) ? oext : (dsel == 1 ? g_h0 : g_h1);

    const int t     = threadIdx.x;
    const int mbase = blockIdx.x * BM;
    const int m0    = (t & 15) * 8;
    const int n0    = (t >> 4) * CN;

    float acc[8][CN];
    #pragma unroll
    for (int i = 0; i < 8; i++)
        #pragma unroll
        for (int j = 0; j < CN; j++) acc[i][j] = 0.f;

    #pragma unroll 1
    for (int kt = 0; kt < KTOT; kt += 32) {
        // stage A tile (transposed): lane = k, iterate rows (coalesced global reads)
        {
            const int kl = t & 31;
            const int k  = kt + kl;
            const float* __restrict__ Asrc = (SPLIT && k >= 64) ? A1 : A0;
            const int kk = (SPLIT && k >= 64) ? (k - 64) : k;
            #pragma unroll
            for (int mm = (t >> 5); mm < BM; mm += 4) {
                int row = mbase + mm;
                As[kl][mm] = (row < NN) ? Asrc[(size_t)row * 64 + kk] : 0.f;
            }
        }
        // stage B tile
        #pragma unroll
        for (int idx = t; idx < 32 * NOUT; idx += 128) {
            int kk = idx / NOUT;
            int c  = idx % NOUT;
            int k  = kt + kk;
            float w = (SPLIT && k >= 64) ? B1[(size_t)(k - 64) * NOUT + c]
                                         : B0[(size_t)k * NOUT + c];
            Bs[kk][c] = w;
        }
        __syncthreads();

        #pragma unroll
        for (int k = 0; k < 32; k++) {
            float4 a0 = *(const float4*)&As[k][m0];
            float4 a1 = *(const float4*)&As[k][m0 + 4];
            float a[8] = {a0.x, a0.y, a0.z, a0.w, a1.x, a1.y, a1.z, a1.w};
            float b[CN];
            if constexpr (CN == 8) {
                float4 b0v = *(const float4*)&Bs[k][n0];
                float4 b1v = *(const float4*)&Bs[k][n0 + 4];
                b[0] = b0v.x; b[1] = b0v.y; b[2] = b0v.z; b[3] = b0v.w;
                b[4] = b1v.x; b[5] = b1v.y; b[6] = b1v.z; b[7] = b1v.w;
            } else {
                float4 b0v = *(const float4*)&Bs[k][n0];
                b[0] = b0v.x; b[1] = b0v.y; b[2] = b0v.z; b[3] = b0v.w;
            }
            #pragma unroll
            for (int i = 0; i < 8; i++)
                #pragma unroll
                for (int j = 0; j < CN; j++)
                    acc[i][j] = fmaf(a[i], b[j], acc[i][j]);
        }
        __syncthreads();
    }

    // epilogue: bias (+ReLU), vectorized stores
    float bv[CN];
    #pragma unroll
    for (int j = 0; j < CN; j++) bv[j] = bias[n0 + j];

    #pragma unroll
    for (int i = 0; i < 8; i++) {
        int row = mbase + m0 + i;
        if (row < NN) {
            float v[CN];
            #pragma unroll
            for (int j = 0; j < CN; j++) {
                float r = acc[i][j] + bv[j];
                if (RELU) r = fmaxf(r, 0.f);
                v[j] = r;
            }
            float* op = &out[(size_t)row * NOUT + n0];
            if constexpr (CN == 8) {
                *(float4*)(op)     = make_float4(v[0], v[1], v[2], v[3]);
                *(float4*)(op + 4) = make_float4(v[4], v[5], v[6], v[7]);
            } else {
                *(float4*)(op) = make_float4(v[0], v[1], v[2], v[3]);
            }
        }
    }
}

// ---------------- host launcher (pure kernel launches; graph-capturable) ----------------
extern "C" void kernel_launch(void* const* d_in, const int* in_sizes, int n_in,
                              void* d_out, int out_size) {
    const float* x    = (const float*)d_in[0];
    const int*   ei   = (const int*)d_in[1];     // int32 edge_index (2, NE)
    const float* Wl1  = (const float*)d_in[2];
    const float* Wr1  = (const float*)d_in[3];
    const float* b1   = (const float*)d_in[4];
    const float* Wl2  = (const float*)d_in[5];
    const float* Wr2  = (const float*)d_in[6];
    const float* b2   = (const float*)d_in[7];
    const float* Wl3  = (const float*)d_in[8];
    const float* Wr3  = (const float*)d_in[9];
    const float* b3   = (const float*)d_in[10];
    const float* Wlin = (const float*)d_in[11];
    const float* blin = (const float*)d_in[12];
    float*       out  = (float*)d_out;

    // CSR build (per launch; deterministic)
    k_zero_deg<<<CDIV(NN, 256), 256>>>();
    k_count<<<CDIV(NE, 256), 256>>>(ei);
    k_scan<<<1, 1024>>>();
    k_scatter<<<CDIV(NE, 256), 256>>>(ei);

    const int AGG_BLOCKS  = CDIV(NN, 8);        // 8 warps/block, warp/node
    const int GEMM_BLOCKS = CDIV(NN, 128);

    // layer 1: agg(x) -> h0 = relu([agg|x]@[Wl1;Wr1]+b1)
    k_agg<<<AGG_BLOCKS, 256>>>(x, 0);
    k_gemm<128, 64, true, true><<<GEMM_BLOCKS, 128>>>(x, 0, 1, Wl1, Wr1, b1, nullptr);
    // layer 2: agg(h0) -> h1
    k_agg<<<AGG_BLOCKS, 256>>>(nullptr, 1);
    k_gemm<128, 64, true, true><<<GEMM_BLOCKS, 128>>>(nullptr, 1, 2, Wl2, Wr2, b2, nullptr);
    // layer 3: agg(h1) -> h0
    k_agg<<<AGG_BLOCKS, 256>>>(nullptr, 2);
    k_gemm<128, 64, true, true><<<GEMM_BLOCKS, 128>>>(nullptr, 2, 1, Wl3, Wr3, b3, nullptr);
    // final linear: out = h0 @ Wlin + blin
    k_gemm<64, 32, false, false><<<GEMM_BLOCKS, 128>>>(nullptr, 1, 0, Wlin, nullptr, blin, out);
}